// round 3
// baseline (speedup 1.0000x reference)
#include <cuda_runtime.h>
#include <cuda_bf16.h>
#include <cstdint>
#include <cstddef>

// ---------------- problem constants ----------------
static constexpr int Tdim = 256, Udim = 64, Hdim = 640, Vdim = 1025;
static constexpr int M_TILE = 128;            // rows per CTA
static constexpr int N_SUBS = 8;              // 8 * 128 = 1024 MMA cols (+1 scalar)
static constexpr int CHUNK_BYTES = 16384;     // B chunk: 128 n x 64 k bf16
static constexpr int NCHUNK = N_SUBS * 10;    // 80 (10 k-chunks of 64 per n-subtile)

// SMEM layout (byte offsets)
static constexpr int SM_SUMS = 0;                         // 128 floats
static constexpr int SM_A    = 1024;                      // 128x640 bf16 = 163840
static constexpr int SM_B    = SM_A + M_TILE * Hdim * 2;  // 164864 (1024-aligned)
static constexpr int SMEM_TOTAL = SM_B + 2 * CHUNK_BYTES; // 197632

// W pre-converted to bf16, pre-swizzled into per-chunk 16KB tiles
__device__ __align__(16) __nv_bfloat16 g_Wb[(size_t)NCHUNK * (CHUNK_BYTES / 2)];

// ---------------- helpers ----------------
__device__ __forceinline__ uint32_t smem_u32(const void* p) {
    uint32_t a;
    asm("{ .reg .u64 t; cvta.to.shared.u64 t, %1; cvt.u32.u64 %0, t; }" : "=r"(a) : "l"(p));
    return a;
}
__device__ __forceinline__ float tanh_a(float x) {
    float y; asm("tanh.approx.f32 %0, %1;" : "=f"(y) : "f"(x)); return y;
}
__device__ __forceinline__ void cp_async16(uint32_t dst, const void* src) {
    asm volatile("cp.async.cg.shared.global [%0], [%1], 16;" :: "r"(dst), "l"(src) : "memory");
}
#define CP_COMMIT() asm volatile("cp.async.commit_group;" ::: "memory")
#define CP_WAIT(n)  asm volatile("cp.async.wait_group %0;" :: "n"(n) : "memory")

#define LDSM_X4(r0, r1, r2, r3, addr) \
    asm volatile("ldmatrix.sync.aligned.m8n8.x4.shared.b16 {%0,%1,%2,%3}, [%4];" \
        : "=r"(r0), "=r"(r1), "=r"(r2), "=r"(r3) : "r"(addr))

#define MMA16816(d, a, b0, b1) \
    asm volatile("mma.sync.aligned.m16n8k16.row.col.f32.bf16.bf16.f32 " \
        "{%0,%1,%2,%3}, {%4,%5,%6,%7}, {%8,%9}, {%0,%1,%2,%3};" \
        : "+f"((d).x), "+f"((d).y), "+f"((d).z), "+f"((d).w) \
        : "r"((a)[0]), "r"((a)[1]), "r"((a)[2]), "r"((a)[3]), "r"(b0), "r"(b1))

// swizzled byte offset inside a [rows x 640] bf16 K-major tile (8r x 64k atoms, SW128)
__device__ __forceinline__ int a_off(int r, int k) {
    int off = (((r >> 3) + ((k >> 6) << 4)) << 10) + ((r & 7) << 7) + ((k & 63) << 1);
    return off ^ ((off >> 3) & 0x70);
}

// ---------------- prologue: W fp32 -> bf16, pre-swizzled per 16KB chunk ----------------
__global__ void conv_w_kernel(const float* __restrict__ W) {
    int i = blockIdx.x * blockDim.x + threadIdx.x;
    if (i >= 1024 * Hdim) return;
    int n = i / Hdim, k = i - n * Hdim;
    float v = W[(size_t)n * Hdim + k];
    int nsb = n >> 7, nn = n & 127, kb = k >> 6, kk = k & 63;
    int off = ((nn >> 3) << 10) + ((nn & 7) << 7) + (kk << 1);
    off ^= (off >> 3) & 0x70;
    int stage = nsb * 10 + kb;
    g_Wb[(size_t)stage * (CHUNK_BYTES / 2) + (off >> 1)] = __float2bfloat16(v);
}

// ---------------- main fused kernel ----------------
__global__ void __launch_bounds__(256, 1) joiner_kernel(
    const float* __restrict__ enc, const float* __restrict__ dec,
    const float* __restrict__ W, const float* __restrict__ bias,
    float* __restrict__ out)
{
    extern __shared__ char smem[];
    const uint32_t sb = smem_u32(smem);
    const int tid = threadIdx.x, lane = tid & 31, wid = tid >> 5;
    float* sums = (float*)smem;  // SM_SUMS
    if (tid < 128) sums[tid] = 0.f;

    // -------- build A = tanh(enc[t] + dec[u]) as bf16, SW128-swizzled --------
    const int m0 = blockIdx.x << 7;
    const int bb = m0 >> 14;              // T*U = 16384 rows per batch
    const int t0 = (m0 & 16383) >> 6;     // 2 t-values per CTA, 64 u each
    {
        const float* encb = enc + ((size_t)bb * Tdim + t0) * Hdim;
        const float* decb = dec + (size_t)bb * Udim * Hdim;
        for (int i = tid; i < M_TILE * (Hdim / 2); i += 256) {
            int r = i / (Hdim / 2);
            int k = (i - r * (Hdim / 2)) << 1;
            const float2 e2 = *(const float2*)(encb + (size_t)(r >> 6) * Hdim + k);
            const float2 d2 = *(const float2*)(decb + (size_t)(r & 63) * Hdim + k);
            *(__nv_bfloat162*)(smem + SM_A + a_off(r, k)) =
                __floats2bfloat162_rn(tanh_a(e2.x + d2.x), tanh_a(e2.y + d2.y));
        }
    }
    __syncthreads();

    // warp grid: 4 (M) x 2 (N); warp tile 32 x 64
    const int mw = wid & 3, nw = wid >> 2;
    // ldmatrix lane decode
    const int a_radd = ((lane >> 3) & 1) << 3, a_kadd = ((lane >> 4) & 1) << 3;
    const int b_kadd = ((lane >> 3) & 1) << 3, b_nadd = ((lane >> 4) & 1) << 3;
    const int rA0 = mw * 32 + a_radd + (lane & 7);   // +16 for i=1
    const int nB0 = nw * 64 + b_nadd + (lane & 7);   // +16 per jm
    const int g = lane >> 2, tq = lane & 3;

    // chunk loader (cp.async, 16 KB, 256 threads x 16B x 4)
    auto load_chunk = [&](int s) {
        const char* src = (const char*)g_Wb + (size_t)s * CHUNK_BYTES;
        uint32_t dst = sb + SM_B + (s & 1) * CHUNK_BYTES;
        #pragma unroll
        for (int j = 0; j < 4; j++) {
            int idx = tid + j * 256;
            cp_async16(dst + idx * 16, src + (size_t)idx * 16);
        }
        CP_COMMIT();
    };
    load_chunk(0);

    float rsum[4] = {0.f, 0.f, 0.f, 0.f};

    for (int nsb = 0; nsb < N_SUBS; nsb++) {
        float4 acc[2][8];
        #pragma unroll
        for (int i = 0; i < 2; i++)
            #pragma unroll
            for (int j = 0; j < 8; j++) acc[i][j] = make_float4(0.f, 0.f, 0.f, 0.f);

        for (int kb = 0; kb < 10; kb++) {
            const int s = nsb * 10 + kb;
            if (s + 1 < NCHUNK) { load_chunk(s + 1); CP_WAIT(1); }
            else                { CP_WAIT(0); }
            __syncthreads();
            const uint32_t bbase = sb + SM_B + (s & 1) * CHUNK_BYTES;

            #pragma unroll
            for (int kk = 0; kk < 4; kk++) {
                uint32_t a[2][4];
                #pragma unroll
                for (int i = 0; i < 2; i++) {
                    const int r = rA0 + i * 16;
                    int rel = (((r >> 3) + (kb << 4)) << 10) + ((r & 7) << 7)
                            + ((kk * 16 + a_kadd) << 1);
                    rel ^= (rel >> 3) & 0x70;
                    LDSM_X4(a[i][0], a[i][1], a[i][2], a[i][3], sb + SM_A + rel);
                }
                uint32_t bq[4][4];
                #pragma unroll
                for (int jm = 0; jm < 4; jm++) {
                    const int n = nB0 + jm * 16;
                    int rel = ((n >> 3) << 10) + ((n & 7) << 7)
                            + ((kk * 16 + b_kadd) << 1);
                    rel ^= (rel >> 3) & 0x70;
                    LDSM_X4(bq[jm][0], bq[jm][1], bq[jm][2], bq[jm][3], bbase + rel);
                }
                #pragma unroll
                for (int i = 0; i < 2; i++)
                    #pragma unroll
                    for (int jm = 0; jm < 4; jm++) {
                        MMA16816(acc[i][2 * jm],     a[i], bq[jm][0], bq[jm][1]);
                        MMA16816(acc[i][2 * jm + 1], a[i], bq[jm][2], bq[jm][3]);
                    }
            }
            __syncthreads();
        }

        // -------- epilogue: bias, expf accumulation, raw logit store --------
        #pragma unroll
        for (int i = 0; i < 2; i++) {
            const int row = mw * 32 + i * 16 + g;
            const size_t base0 = (size_t)(m0 + row) * Vdim;
            const size_t base1 = base0 + 8 * (size_t)Vdim;
            #pragma unroll
            for (int j = 0; j < 8; j++) {
                const int col = nsb * 128 + nw * 64 + j * 8 + tq * 2;
                const float bi0 = __ldg(bias + col), bi1 = __ldg(bias + col + 1);
                const float4 c = acc[i][j];
                const float v0 = c.x + bi0, v1 = c.y + bi1;
                const float v2 = c.z + bi0, v3 = c.w + bi1;
                rsum[2 * i]     += __expf(v0) + __expf(v1);
                rsum[2 * i + 1] += __expf(v2) + __expf(v3);
                // Vdim is odd -> row bases alternate 8B alignment: scalar stores only
                out[base0 + col] = v0; out[base0 + col + 1] = v1;
                out[base1 + col] = v2; out[base1 + col + 1] = v3;
            }
        }
    }

    // -------- scalar column v = 1024 --------
    {
        const int r = tid >> 1, half = tid & 1;
        float acc = 0.f;
        const float* w1 = W + (size_t)1024 * Hdim;
        const int k0 = half * 320;
        #pragma unroll 4
        for (int k = k0; k < k0 + 320; k += 2) {
            const __nv_bfloat162 hv = *(const __nv_bfloat162*)(smem + SM_A + a_off(r, k));
            const float2 hf = __bfloat1622float2(hv);
            acc += hf.x * __ldg(w1 + k) + hf.y * __ldg(w1 + k + 1);
        }
        acc += __shfl_xor_sync(0xffffffffu, acc, 1);
        if (half == 0) {
            const float v = acc + __ldg(bias + 1024);
            out[(size_t)(m0 + r) * Vdim + 1024] = v;
            atomicAdd(&sums[r], __expf(v));
        }
    }
    // -------- accumulate row sums --------
    #pragma unroll
    for (int i = 0; i < 2; i++) {
        atomicAdd(&sums[mw * 32 + i * 16 + g],     rsum[2 * i]);
        atomicAdd(&sums[mw * 32 + i * 16 + g + 8], rsum[2 * i + 1]);
    }
    __syncthreads();
    if (tid < 128) sums[tid] = __logf(sums[tid]);
    __syncthreads();

    // -------- correction pass: out -= log(sumexp) (reads mostly L2 hits) --------
    for (int r = 0; r < M_TILE; r++) {
        const float l = sums[r];
        const size_t base = (size_t)(m0 + r) * Vdim;
        for (int c = tid; c < Vdim; c += 256) out[base + c] -= l;
    }
}

// ---------------- launch ----------------
extern "C" void kernel_launch(void* const* d_in, const int* in_sizes, int n_in,
                              void* d_out, int out_size) {
    const float* enc  = (const float*)d_in[0];
    const float* dec  = (const float*)d_in[1];
    const float* W    = (const float*)d_in[2];
    const float* bias = (const float*)d_in[3];
    float* out = (float*)d_out;

    conv_w_kernel<<<(1024 * Hdim + 255) / 256, 256>>>(W);

    static bool attr_set = false;
    if (!attr_set) {
        cudaFuncSetAttribute(joiner_kernel,
                             cudaFuncAttributeMaxDynamicSharedMemorySize, SMEM_TOTAL);
        attr_set = true;
    }
    joiner_kernel<<<1024, 256, SMEM_TOTAL>>>(enc, dec, W, bias, out);
}

// round 4
// speedup vs baseline: 1.2559x; 1.2559x over previous
#include <cuda_runtime.h>
#include <cuda_bf16.h>
#include <cstdint>
#include <cstddef>

// ---------------- problem constants ----------------
static constexpr int Tdim = 256, Udim = 64, Hdim = 640, Vdim = 1025;
static constexpr int M_TILE = 128;            // rows per CTA
static constexpr int N_SUBS = 8;              // 8 * 128 = 1024 MMA cols (+1 scalar)
static constexpr int CHUNK_BYTES = 16384;     // B chunk: 128 n x 64 k bf16
static constexpr int NCHUNK = N_SUBS * 10;    // 80
static constexpr int NSTAGE = 4;              // cp.async ring depth
static constexpr int NTHREADS = 512;

// SMEM layout (byte offsets)
static constexpr int SM_SUMS = 0;                         // 128 floats
static constexpr int SM_A    = 1024;                      // 128x640 bf16 = 163840
static constexpr int SM_B    = SM_A + M_TILE * Hdim * 2;  // 164864 (1024-aligned)
static constexpr int SMEM_TOTAL = SM_B + NSTAGE * CHUNK_BYTES; // 230400

// W pre-converted to bf16, pre-swizzled into per-chunk 16KB tiles
__device__ __align__(16) __nv_bfloat16 g_Wb[(size_t)NCHUNK * (CHUNK_BYTES / 2)];

// ---------------- helpers ----------------
__device__ __forceinline__ uint32_t smem_u32(const void* p) {
    uint32_t a;
    asm("{ .reg .u64 t; cvta.to.shared.u64 t, %1; cvt.u32.u64 %0, t; }" : "=r"(a) : "l"(p));
    return a;
}
__device__ __forceinline__ float tanh_a(float x) {
    float y; asm("tanh.approx.f32 %0, %1;" : "=f"(y) : "f"(x)); return y;
}
__device__ __forceinline__ void cp_async16(uint32_t dst, const void* src) {
    asm volatile("cp.async.cg.shared.global [%0], [%1], 16;" :: "r"(dst), "l"(src) : "memory");
}
#define CP_COMMIT() asm volatile("cp.async.commit_group;" ::: "memory")
#define CP_WAIT(n)  asm volatile("cp.async.wait_group %0;" :: "n"(n) : "memory")

#define LDSM_X4(r0, r1, r2, r3, addr) \
    asm volatile("ldmatrix.sync.aligned.m8n8.x4.shared.b16 {%0,%1,%2,%3}, [%4];" \
        : "=r"(r0), "=r"(r1), "=r"(r2), "=r"(r3) : "r"(addr))

#define MMA16816(d, a, b0, b1) \
    asm volatile("mma.sync.aligned.m16n8k16.row.col.f32.bf16.bf16.f32 " \
        "{%0,%1,%2,%3}, {%4,%5,%6,%7}, {%8,%9}, {%0,%1,%2,%3};" \
        : "+f"((d).x), "+f"((d).y), "+f"((d).z), "+f"((d).w) \
        : "r"((a)[0]), "r"((a)[1]), "r"((a)[2]), "r"((a)[3]), "r"(b0), "r"(b1))

// swizzled byte offset inside a [rows x 640] bf16 K-major tile (8r x 64k atoms, SW128)
__device__ __forceinline__ int a_off(int r, int k) {
    int off = (((r >> 3) + ((k >> 6) << 4)) << 10) + ((r & 7) << 7) + ((k & 63) << 1);
    return off ^ ((off >> 3) & 0x70);
}

// ---------------- prologue: W fp32 -> bf16, pre-swizzled per 16KB chunk ----------------
__global__ void conv_w_kernel(const float* __restrict__ W) {
    int i = blockIdx.x * blockDim.x + threadIdx.x;
    if (i >= 1024 * Hdim) return;
    int n = i / Hdim, k = i - n * Hdim;
    float v = W[(size_t)n * Hdim + k];
    int nsb = n >> 7, nn = n & 127, kb = k >> 6, kk = k & 63;
    int off = ((nn >> 3) << 10) + ((nn & 7) << 7) + (kk << 1);
    off ^= (off >> 3) & 0x70;
    int stage = nsb * 10 + kb;
    g_Wb[(size_t)stage * (CHUNK_BYTES / 2) + (off >> 1)] = __float2bfloat16(v);
}

// ---------------- main fused kernel ----------------
__global__ void __launch_bounds__(NTHREADS, 1) joiner_kernel(
    const float* __restrict__ enc, const float* __restrict__ dec,
    const float* __restrict__ W, const float* __restrict__ bias,
    float* __restrict__ out)
{
    extern __shared__ char smem[];
    const uint32_t sb = smem_u32(smem);
    const int tid = threadIdx.x, lane = tid & 31, wid = tid >> 5;
    float* sums = (float*)smem;  // SM_SUMS
    if (tid < 128) sums[tid] = 0.f;

    // chunk loader: 16 KB via cp.async, 512 threads x 2 x 16B
    auto load_chunk = [&](int s) {
        const char* src = (const char*)g_Wb + (size_t)s * CHUNK_BYTES;
        uint32_t dst = sb + SM_B + (s & (NSTAGE - 1)) * CHUNK_BYTES;
        #pragma unroll
        for (int j = 0; j < 2; j++) {
            int idx = tid + j * NTHREADS;
            cp_async16(dst + idx * 16, src + (size_t)idx * 16);
        }
        CP_COMMIT();
    };
    // start streaming W immediately; overlaps with A-tile build
    load_chunk(0);
    load_chunk(1);

    // -------- build A = tanh(enc[t] + dec[u]) as bf16, SW128-swizzled --------
    const int m0 = blockIdx.x << 7;
    const int bb = m0 >> 14;              // T*U = 16384 rows per batch
    const int t0 = (m0 & 16383) >> 6;     // 2 t-values per CTA, 64 u each
    {
        const float* encb = enc + ((size_t)bb * Tdim + t0) * Hdim;
        const float* decb = dec + (size_t)bb * Udim * Hdim;
        for (int i = tid; i < M_TILE * (Hdim / 2); i += NTHREADS) {
            int r = i / (Hdim / 2);
            int k = (i - r * (Hdim / 2)) << 1;
            const float2 e2 = *(const float2*)(encb + (size_t)(r >> 6) * Hdim + k);
            const float2 d2 = *(const float2*)(decb + (size_t)(r & 63) * Hdim + k);
            *(__nv_bfloat162*)(smem + SM_A + a_off(r, k)) =
                __floats2bfloat162_rn(tanh_a(e2.x + d2.x), tanh_a(e2.y + d2.y));
        }
    }
    __syncthreads();

    // warp grid: 4 (M) x 4 (N); warp tile 32 x 32
    const int mw = wid & 3, nw = wid >> 2;
    // ldmatrix lane decode
    const int a_radd = ((lane >> 3) & 1) << 3, a_kadd = ((lane >> 4) & 1) << 3;
    const int b_kadd = ((lane >> 3) & 1) << 3, b_nadd = ((lane >> 4) & 1) << 3;
    const int rA0 = mw * 32 + a_radd + (lane & 7);   // +16 for i=1
    const int nB0 = nw * 32 + b_nadd + (lane & 7);   // +16 for jm=1
    const int g = lane >> 2, tq = lane & 3;

    float rsum[4] = {0.f, 0.f, 0.f, 0.f};

    for (int nsb = 0; nsb < N_SUBS; nsb++) {
        float4 acc[2][4];
        #pragma unroll
        for (int i = 0; i < 2; i++)
            #pragma unroll
            for (int j = 0; j < 4; j++) acc[i][j] = make_float4(0.f, 0.f, 0.f, 0.f);

        for (int kb = 0; kb < 10; kb++) {
            const int s = nsb * 10 + kb;
            // prefetch distance 2 into 4-slot ring; slot (s+2)&3 cannot collide
            // with oldest possible in-flight compute (s-1)
            if (s + 2 < NCHUNK)      { load_chunk(s + 2); CP_WAIT(2); }
            else if (s + 1 < NCHUNK) { CP_WAIT(1); }
            else                     { CP_WAIT(0); }
            __syncthreads();
            const uint32_t bbase = sb + SM_B + (s & (NSTAGE - 1)) * CHUNK_BYTES;

            #pragma unroll
            for (int kk = 0; kk < 4; kk++) {
                uint32_t a[2][4];
                #pragma unroll
                for (int i = 0; i < 2; i++) {
                    const int r = rA0 + i * 16;
                    int rel = (((r >> 3) + (kb << 4)) << 10) + ((r & 7) << 7)
                            + ((kk * 16 + a_kadd) << 1);
                    rel ^= (rel >> 3) & 0x70;
                    LDSM_X4(a[i][0], a[i][1], a[i][2], a[i][3], sb + SM_A + rel);
                }
                uint32_t bq[2][4];
                #pragma unroll
                for (int jm = 0; jm < 2; jm++) {
                    const int n = nB0 + jm * 16;
                    int rel = ((n >> 3) << 10) + ((n & 7) << 7)
                            + ((kk * 16 + b_kadd) << 1);
                    rel ^= (rel >> 3) & 0x70;
                    LDSM_X4(bq[jm][0], bq[jm][1], bq[jm][2], bq[jm][3], bbase + rel);
                }
                #pragma unroll
                for (int i = 0; i < 2; i++)
                    #pragma unroll
                    for (int jm = 0; jm < 2; jm++) {
                        MMA16816(acc[i][2 * jm],     a[i], bq[jm][0], bq[jm][1]);
                        MMA16816(acc[i][2 * jm + 1], a[i], bq[jm][2], bq[jm][3]);
                    }
            }
        }

        // -------- epilogue: bias, expf accumulation, raw logit store --------
        #pragma unroll
        for (int i = 0; i < 2; i++) {
            const int row = mw * 32 + i * 16 + g;
            const size_t base0 = (size_t)(m0 + row) * Vdim;
            const size_t base1 = base0 + 8 * (size_t)Vdim;
            #pragma unroll
            for (int j = 0; j < 4; j++) {
                const int col = nsb * 128 + nw * 32 + j * 8 + tq * 2;
                const float bi0 = __ldg(bias + col), bi1 = __ldg(bias + col + 1);
                const float4 c = acc[i][j];
                const float v0 = c.x + bi0, v1 = c.y + bi1;
                const float v2 = c.z + bi0, v3 = c.w + bi1;
                rsum[2 * i]     += __expf(v0) + __expf(v1);
                rsum[2 * i + 1] += __expf(v2) + __expf(v3);
                // Vdim odd -> alternating row alignment: scalar stores
                out[base0 + col] = v0; out[base0 + col + 1] = v1;
                out[base1 + col] = v2; out[base1 + col + 1] = v3;
            }
        }
    }

    // -------- scalar column v = 1024 --------
    {
        const int r = tid >> 2, q = tid & 3;
        float acc = 0.f;
        const float* w1 = W + (size_t)1024 * Hdim;
        const int k0 = q * 160;
        #pragma unroll 4
        for (int k = k0; k < k0 + 160; k += 2) {
            const __nv_bfloat162 hv = *(const __nv_bfloat162*)(smem + SM_A + a_off(r, k));
            const float2 hf = __bfloat1622float2(hv);
            acc += hf.x * __ldg(w1 + k) + hf.y * __ldg(w1 + k + 1);
        }
        acc += __shfl_xor_sync(0xffffffffu, acc, 1);
        acc += __shfl_xor_sync(0xffffffffu, acc, 2);
        if (q == 0) {
            const float v = acc + __ldg(bias + 1024);
            out[(size_t)(m0 + r) * Vdim + 1024] = v;
            atomicAdd(&sums[r], __expf(v));
        }
    }
    // -------- accumulate row sums --------
    #pragma unroll
    for (int i = 0; i < 2; i++) {
        atomicAdd(&sums[mw * 32 + i * 16 + g],     rsum[2 * i]);
        atomicAdd(&sums[mw * 32 + i * 16 + g + 8], rsum[2 * i + 1]);
    }
    __syncthreads();
    if (tid < 128) sums[tid] = __logf(sums[tid]);
    __syncthreads();

    // -------- correction pass: out -= log(sumexp) (reads mostly L2 hits) --------
    for (int r = 0; r < M_TILE; r++) {
        const float l = sums[r];
        const size_t base = (size_t)(m0 + r) * Vdim;
        for (int c = tid; c < Vdim; c += NTHREADS) out[base + c] -= l;
    }
}

// ---------------- launch ----------------
extern "C" void kernel_launch(void* const* d_in, const int* in_sizes, int n_in,
                              void* d_out, int out_size) {
    const float* enc  = (const float*)d_in[0];
    const float* dec  = (const float*)d_in[1];
    const float* W    = (const float*)d_in[2];
    const float* bias = (const float*)d_in[3];
    float* out = (float*)d_out;

    conv_w_kernel<<<(1024 * Hdim + 255) / 256, 256>>>(W);

    static bool attr_set = false;
    if (!attr_set) {
        cudaFuncSetAttribute(joiner_kernel,
                             cudaFuncAttributeMaxDynamicSharedMemorySize, SMEM_TOTAL);
        attr_set = true;
    }
    joiner_kernel<<<1024, NTHREADS, SMEM_TOTAL>>>(enc, dec, W, bias, out);
}

// round 5
// speedup vs baseline: 1.2817x; 1.0205x over previous
#include <cuda_runtime.h>
#include <cuda_bf16.h>
#include <cstdint>
#include <cstddef>

// ---------------- problem constants ----------------
static constexpr int Tdim = 256, Udim = 64, Hdim = 640, Vdim = 1025;
static constexpr int M_TILE = 128;            // rows per CTA
static constexpr int N_SUBS = 8;              // 8 * 128 = 1024 MMA cols (+1 scalar)
static constexpr int CHUNK_BYTES = 32768;     // B chunk: 128 n x 128 k bf16
static constexpr int KB_PER_NSB = 5;          // 640 / 128
static constexpr int NCHUNK = N_SUBS * KB_PER_NSB; // 40
static constexpr int NTHREADS = 512;

// SMEM layout (byte offsets)
static constexpr int SM_SUMS = 0;                         // 128 floats
static constexpr int SM_A    = 1024;                      // 128x640 bf16 = 163840
static constexpr int SM_B    = SM_A + M_TILE * Hdim * 2;  // 164864 (1024-aligned)
static constexpr int SMEM_TOTAL = SM_B + 2 * CHUNK_BYTES; // 230400 (< 232448 max)

// W pre-converted to bf16, pre-swizzled into per-chunk 32KB tiles
__device__ __align__(16) __nv_bfloat16 g_Wb[(size_t)NCHUNK * (CHUNK_BYTES / 2)];

// ---------------- helpers ----------------
__device__ __forceinline__ uint32_t smem_u32(const void* p) {
    uint32_t a;
    asm("{ .reg .u64 t; cvta.to.shared.u64 t, %1; cvt.u32.u64 %0, t; }" : "=r"(a) : "l"(p));
    return a;
}
__device__ __forceinline__ float tanh_a(float x) {
    float y; asm("tanh.approx.f32 %0, %1;" : "=f"(y) : "f"(x)); return y;
}
__device__ __forceinline__ void cp_async16(uint32_t dst, const void* src) {
    asm volatile("cp.async.cg.shared.global [%0], [%1], 16;" :: "r"(dst), "l"(src) : "memory");
}
#define CP_COMMIT() asm volatile("cp.async.commit_group;" ::: "memory")
#define CP_WAIT(n)  asm volatile("cp.async.wait_group %0;" :: "n"(n) : "memory")

#define LDSM_X4(r0, r1, r2, r3, addr) \
    asm volatile("ldmatrix.sync.aligned.m8n8.x4.shared.b16 {%0,%1,%2,%3}, [%4];" \
        : "=r"(r0), "=r"(r1), "=r"(r2), "=r"(r3) : "r"(addr))

#define MMA16816(d, a, b0, b1) \
    asm volatile("mma.sync.aligned.m16n8k16.row.col.f32.bf16.bf16.f32 " \
        "{%0,%1,%2,%3}, {%4,%5,%6,%7}, {%8,%9}, {%0,%1,%2,%3};" \
        : "+f"((d).x), "+f"((d).y), "+f"((d).z), "+f"((d).w) \
        : "r"((a)[0]), "r"((a)[1]), "r"((a)[2]), "r"((a)[3]), "r"(b0), "r"(b1))

// swizzled byte offset for a 128-row bf16 K-major tile (8r x 64k atoms, SW128,
// atom-column stride = 16 groups * 1024B). Works for both the A tile and B chunks.
__device__ __forceinline__ int a_off(int r, int k) {
    int off = (((r >> 3) + ((k >> 6) << 4)) << 10) + ((r & 7) << 7) + ((k & 63) << 1);
    return off ^ ((off >> 3) & 0x70);
}

// ---------------- prologue: W fp32 -> bf16, pre-swizzled per 32KB chunk ----------------
__global__ void conv_w_kernel(const float* __restrict__ W) {
    int i = blockIdx.x * blockDim.x + threadIdx.x;
    if (i >= 1024 * Hdim) return;
    int n = i / Hdim, k = i - n * Hdim;
    float v = W[(size_t)n * Hdim + k];
    int nsb = n >> 7, nn = n & 127, kb2 = k >> 7, kp = k & 127;
    int off = (((nn >> 3) + ((kp >> 6) << 4)) << 10) + ((nn & 7) << 7) + ((kp & 63) << 1);
    off ^= (off >> 3) & 0x70;
    int stage = nsb * KB_PER_NSB + kb2;
    g_Wb[(size_t)stage * (CHUNK_BYTES / 2) + (off >> 1)] = __float2bfloat16(v);
}

// ---------------- main fused kernel ----------------
__global__ void __launch_bounds__(NTHREADS, 1) joiner_kernel(
    const float* __restrict__ enc, const float* __restrict__ dec,
    const float* __restrict__ W, const float* __restrict__ bias,
    float* __restrict__ out)
{
    extern __shared__ char smem[];
    const uint32_t sb = smem_u32(smem);
    const int tid = threadIdx.x, lane = tid & 31, wid = tid >> 5;
    float* sums = (float*)smem;  // SM_SUMS
    if (tid < 128) sums[tid] = 0.f;

    // chunk loader: 32 KB via cp.async, 512 threads x 4 x 16B; one commit group per chunk
    auto load_chunk = [&](int s) {
        const char* src = (const char*)g_Wb + (size_t)s * CHUNK_BYTES;
        uint32_t dst = sb + SM_B + (s & 1) * CHUNK_BYTES;
        #pragma unroll
        for (int j = 0; j < 4; j++) {
            int idx = tid + j * NTHREADS;
            cp_async16(dst + idx * 16, src + (size_t)idx * 16);
        }
        CP_COMMIT();
    };
    load_chunk(0);  // overlaps with A-tile build

    // -------- build A = tanh(enc[t] + dec[u]) as bf16, SW128-swizzled --------
    const int m0 = blockIdx.x << 7;
    const int bb = m0 >> 14;              // T*U = 16384 rows per batch
    const int t0 = (m0 & 16383) >> 6;     // 2 t-values per CTA, 64 u each
    {
        const float* encb = enc + ((size_t)bb * Tdim + t0) * Hdim;
        const float* decb = dec + (size_t)bb * Udim * Hdim;
        for (int i = tid; i < M_TILE * (Hdim / 2); i += NTHREADS) {
            int r = i / (Hdim / 2);
            int k = (i - r * (Hdim / 2)) << 1;
            const float2 e2 = *(const float2*)(encb + (size_t)(r >> 6) * Hdim + k);
            const float2 d2 = *(const float2*)(decb + (size_t)(r & 63) * Hdim + k);
            *(__nv_bfloat162*)(smem + SM_A + a_off(r, k)) =
                __floats2bfloat162_rn(tanh_a(e2.x + d2.x), tanh_a(e2.y + d2.y));
        }
    }
    // NOTE: no standalone barrier here — iteration 0's __syncthreads covers A visibility.

    // warp grid: 4 (M) x 4 (N); warp tile 32 x 32
    const int mw = wid & 3, nw = wid >> 2;
    const int a_radd = ((lane >> 3) & 1) << 3, a_kadd = ((lane >> 4) & 1) << 3;
    const int b_kadd = ((lane >> 3) & 1) << 3, b_nadd = ((lane >> 4) & 1) << 3;
    const int rA0 = mw * 32 + a_radd + (lane & 7);   // +16 for i=1
    const int nB0 = nw * 32 + b_nadd + (lane & 7);   // +16 for jm=1
    const int g = lane >> 2, tq = lane & 3;

    float rsum[4] = {0.f, 0.f, 0.f, 0.f};

    for (int nsb = 0; nsb < N_SUBS; nsb++) {
        float4 acc[2][4];
        #pragma unroll
        for (int i = 0; i < 2; i++)
            #pragma unroll
            for (int j = 0; j < 4; j++) acc[i][j] = make_float4(0.f, 0.f, 0.f, 0.f);

        for (int kb2 = 0; kb2 < KB_PER_NSB; kb2++) {
            const int s = nsb * KB_PER_NSB + kb2;
            CP_WAIT(0);          // chunk s landed (issued last iteration)
            __syncthreads();     // all warps done with chunk s-1 -> buffer (s+1)&1 free
            if (s + 1 < NCHUNK) load_chunk(s + 1);
            const uint32_t bbase = sb + SM_B + (s & 1) * CHUNK_BYTES;

            // B fragments double-buffered across the 8 kk steps
            uint32_t bq[2][2][4];
            #pragma unroll
            for (int jm = 0; jm < 2; jm++) {
                const int n = nB0 + jm * 16;
                int rel = a_off(n, b_kadd);
                LDSM_X4(bq[0][jm][0], bq[0][jm][1], bq[0][jm][2], bq[0][jm][3], bbase + rel);
            }
            #pragma unroll
            for (int kk = 0; kk < 8; kk++) {
                const int cur = kk & 1, nxt = cur ^ 1;
                if (kk < 7) {
                    #pragma unroll
                    for (int jm = 0; jm < 2; jm++) {
                        const int n = nB0 + jm * 16;
                        int rel = a_off(n, (kk + 1) * 16 + b_kadd);
                        LDSM_X4(bq[nxt][jm][0], bq[nxt][jm][1], bq[nxt][jm][2], bq[nxt][jm][3],
                                bbase + rel);
                    }
                }
                uint32_t a[2][4];
                #pragma unroll
                for (int i = 0; i < 2; i++) {
                    const int r = rA0 + i * 16;
                    int rel = a_off(r, kb2 * 128 + kk * 16 + a_kadd);
                    LDSM_X4(a[i][0], a[i][1], a[i][2], a[i][3], sb + SM_A + rel);
                }
                #pragma unroll
                for (int i = 0; i < 2; i++)
                    #pragma unroll
                    for (int jm = 0; jm < 2; jm++) {
                        MMA16816(acc[i][2 * jm],     a[i], bq[cur][jm][0], bq[cur][jm][1]);
                        MMA16816(acc[i][2 * jm + 1], a[i], bq[cur][jm][2], bq[cur][jm][3]);
                    }
            }
        }

        // -------- epilogue: bias, expf accumulation, raw logit store --------
        // (next chunk's cp.async already in flight -> overlaps this)
        #pragma unroll
        for (int i = 0; i < 2; i++) {
            const int row = mw * 32 + i * 16 + g;
            const size_t base0 = (size_t)(m0 + row) * Vdim;
            const size_t base1 = base0 + 8 * (size_t)Vdim;
            #pragma unroll
            for (int j = 0; j < 4; j++) {
                const int col = nsb * 128 + nw * 32 + j * 8 + tq * 2;
                const float bi0 = __ldg(bias + col), bi1 = __ldg(bias + col + 1);
                const float4 c = acc[i][j];
                const float v0 = c.x + bi0, v1 = c.y + bi1;
                const float v2 = c.z + bi0, v3 = c.w + bi1;
                rsum[2 * i]     += __expf(v0) + __expf(v1);
                rsum[2 * i + 1] += __expf(v2) + __expf(v3);
                // Vdim odd -> alternating row alignment: scalar stores
                out[base0 + col] = v0; out[base0 + col + 1] = v1;
                out[base1 + col] = v2; out[base1 + col + 1] = v3;
            }
        }
    }

    // -------- scalar column v = 1024 --------
    {
        const int r = tid >> 2, q = tid & 3;
        float acc = 0.f;
        const float* w1 = W + (size_t)1024 * Hdim;
        const int k0 = q * 160;
        #pragma unroll 4
        for (int k = k0; k < k0 + 160; k += 2) {
            const __nv_bfloat162 hv = *(const __nv_bfloat162*)(smem + SM_A + a_off(r, k));
            const float2 hf = __bfloat1622float2(hv);
            acc += hf.x * __ldg(w1 + k) + hf.y * __ldg(w1 + k + 1);
        }
        acc += __shfl_xor_sync(0xffffffffu, acc, 1);
        acc += __shfl_xor_sync(0xffffffffu, acc, 2);
        if (q == 0) {
            const float v = acc + __ldg(bias + 1024);
            out[(size_t)(m0 + r) * Vdim + 1024] = v;
            atomicAdd(&sums[r], __expf(v));
        }
    }
    // -------- accumulate row sums --------
    #pragma unroll
    for (int i = 0; i < 2; i++) {
        atomicAdd(&sums[mw * 32 + i * 16 + g],     rsum[2 * i]);
        atomicAdd(&sums[mw * 32 + i * 16 + g + 8], rsum[2 * i + 1]);
    }
    __syncthreads();
    if (tid < 128) sums[tid] = __logf(sums[tid]);
    __syncthreads();

    // -------- correction pass: out -= log(sumexp) (reads mostly L2 hits) --------
    for (int r = 0; r < M_TILE; r++) {
        const float l = sums[r];
        const size_t base = (size_t)(m0 + r) * Vdim;
        for (int c = tid; c < Vdim; c += NTHREADS) out[base + c] -= l;
    }
}

// ---------------- launch ----------------
extern "C" void kernel_launch(void* const* d_in, const int* in_sizes, int n_in,
                              void* d_out, int out_size) {
    const float* enc  = (const float*)d_in[0];
    const float* dec  = (const float*)d_in[1];
    const float* W    = (const float*)d_in[2];
    const float* bias = (const float*)d_in[3];
    float* out = (float*)d_out;

    conv_w_kernel<<<(1024 * Hdim + 255) / 256, 256>>>(W);

    static bool attr_set = false;
    if (!attr_set) {
        cudaFuncSetAttribute(joiner_kernel,
                             cudaFuncAttributeMaxDynamicSharedMemorySize, SMEM_TOTAL);
        attr_set = true;
    }
    joiner_kernel<<<1024, NTHREADS, SMEM_TOTAL>>>(enc, dec, W, bias, out);
}